// round 4
// baseline (speedup 1.0000x reference)
#include <cuda_runtime.h>
#include <cuda_fp16.h>
#include <cstdint>

// jordon_combined_layer: out[b] = ob + sum_u sigmoid(x[b,:]@W[:,u] + bias[u] + state*state_W[u]) * oW[u]
// B = 2097152, D = U = 64, L = 1. Output fp32 [B,1].
//
// Base-target design (harness compiles PTX for compute_103, so no tcgen05/TMA):
//   - legacy mma.sync m16n8k16 f16 (HMMA), fp32 accumulate
//   - x loaded straight from GMEM in fragment ownership (float2 per lane), cvt to half2
//   - W fragments precomputed once per CTA into an 8 KB SMEM table
//   - sigmoid via 0.5 + 0.5*tanh(z/2)  (1 MUFU per element)
//   - fused output dot + warp-shuffle reduce, one STG.32 per row

#define ITERS 8
#define ROWS_PER_ITER 64          // 4 warps * 16 rows
#define ROWS_PER_CTA  (ITERS * ROWS_PER_ITER)   // 512

#define MMA16816(c0, c1, c2, c3, a0, a1, a2, a3, b0, b1)                         \
    asm volatile(                                                                \
        "mma.sync.aligned.m16n8k16.row.col.f32.f16.f16.f32 "                     \
        "{%0,%1,%2,%3}, {%4,%5,%6,%7}, {%8,%9}, {%0,%1,%2,%3};"                  \
        : "+f"(c0), "+f"(c1), "+f"(c2), "+f"(c3)                                 \
        : "r"(a0), "r"(a1), "r"(a2), "r"(a3), "r"(b0), "r"(b1))

static __device__ __forceinline__ uint32_t h2bits(__half2 h) {
    return *reinterpret_cast<uint32_t*>(&h);
}

__global__ void __launch_bounds__(128)
jordon_kernel(const float* __restrict__ x,
              const float* __restrict__ state,
              const float* __restrict__ inW,
              const float* __restrict__ stW,
              const float* __restrict__ bias,
              const float* __restrict__ outW,
              const float* __restrict__ outb,
              float* __restrict__ out) {
    // W fragment table: [k-step][n-tile][lane] -> {b0, b1} (half2 bit patterns)
    __shared__ uint2  btab[4][8][32];
    // per-(n-tile, tg) constants: {0.5*(b+s)_u0, 0.5*oW_u0, 0.5*(b+s)_u1, 0.5*oW_u1}
    __shared__ float4 cwv[32];
    __shared__ float  ob;

    const int tid  = threadIdx.x;
    const int wid  = tid >> 5;
    const int lane = tid & 31;
    const int g    = lane >> 2;   // group id (row within fragment)
    const int tg   = lane & 3;    // thread-in-group (col pair)

    // ---- prologue: constants ----
    if (tid < 32) {
        int j  = tid >> 2;
        int t4 = tid & 3;
        int u0 = j * 8 + t4 * 2;
        float s  = state[0];
        float s0 = s * stW[u0];
        float s1 = s * stW[u0 + 1];
        cwv[tid] = make_float4(0.5f * (bias[u0] + s0),     0.5f * outW[u0],
                               0.5f * (bias[u0 + 1] + s1), 0.5f * outW[u0 + 1]);
    }
    if (tid == 32) ob = outb[0];

    // ---- prologue: W fragment table (warp 0 only; lane-indexed, warp-invariant) ----
    if (wid == 0) {
#pragma unroll
        for (int k = 0; k < 4; k++) {
#pragma unroll
            for (int j = 0; j < 8; j++) {
                int r = k * 16 + tg * 2;   // K index
                int c = j * 8 + g;         // N index (u)
                __half2 lo = __floats2half2_rn(inW[(r    ) * 64 + c], inW[(r + 1) * 64 + c]);
                __half2 hi = __floats2half2_rn(inW[(r + 8) * 64 + c], inW[(r + 9) * 64 + c]);
                btab[k][j][lane] = make_uint2(h2bits(lo), h2bits(hi));
            }
        }
    }
    __syncthreads();

    const size_t cta_row = (size_t)blockIdx.x * ROWS_PER_CTA + (size_t)wid * 16;

#pragma unroll 1
    for (int it = 0; it < ITERS; it++) {
        const size_t R  = cta_row + (size_t)it * ROWS_PER_ITER;
        const float* xr = x + R * 64;

        // ---- A fragments: 16 independent float2 LDGs (high MLP), cvt to half2 ----
        uint32_t af[4][4];
#pragma unroll
        for (int k = 0; k < 4; k++) {
            int c0 = k * 16 + tg * 2;
            float2 v0 = *reinterpret_cast<const float2*>(xr + (size_t)(g    ) * 64 + c0);
            float2 v1 = *reinterpret_cast<const float2*>(xr + (size_t)(g + 8) * 64 + c0);
            float2 v2 = *reinterpret_cast<const float2*>(xr + (size_t)(g    ) * 64 + c0 + 8);
            float2 v3 = *reinterpret_cast<const float2*>(xr + (size_t)(g + 8) * 64 + c0 + 8);
            af[k][0] = h2bits(__float22half2_rn(v0));
            af[k][1] = h2bits(__float22half2_rn(v1));
            af[k][2] = h2bits(__float22half2_rn(v2));
            af[k][3] = h2bits(__float22half2_rn(v3));
        }

        // ---- MMA: 4 k-steps x 8 n-tiles, fp32 accumulate ----
        float acc[8][4];
#pragma unroll
        for (int j = 0; j < 8; j++) {
            acc[j][0] = 0.f; acc[j][1] = 0.f; acc[j][2] = 0.f; acc[j][3] = 0.f;
        }
#pragma unroll
        for (int k = 0; k < 4; k++) {
#pragma unroll
            for (int j = 0; j < 8; j++) {
                uint2 bb = btab[k][j][lane];
                MMA16816(acc[j][0], acc[j][1], acc[j][2], acc[j][3],
                         af[k][0], af[k][1], af[k][2], af[k][3], bb.x, bb.y);
            }
        }

        // ---- epilogue: sigmoid(z)*oW summed over this thread's 16 u's per row ----
        // sigmoid(z) = 0.5 + 0.5*tanh(z/2);  sigmoid(z)*oW = fma(tanh(z/2), oW/2, oW/2)
        float p0 = 0.f, p1 = 0.f;
#pragma unroll
        for (int j = 0; j < 8; j++) {
            float4 w = cwv[j * 4 + tg];
            float t;
            float v;

            v = fmaf(acc[j][0], 0.5f, w.x);
            asm("tanh.approx.f32 %0, %1;" : "=f"(t) : "f"(v));
            p0 += fmaf(t, w.y, w.y);

            v = fmaf(acc[j][1], 0.5f, w.z);
            asm("tanh.approx.f32 %0, %1;" : "=f"(t) : "f"(v));
            p0 += fmaf(t, w.w, w.w);

            v = fmaf(acc[j][2], 0.5f, w.x);
            asm("tanh.approx.f32 %0, %1;" : "=f"(t) : "f"(v));
            p1 += fmaf(t, w.y, w.y);

            v = fmaf(acc[j][3], 0.5f, w.z);
            asm("tanh.approx.f32 %0, %1;" : "=f"(t) : "f"(v));
            p1 += fmaf(t, w.w, w.w);
        }

        // reduce across the 4 lanes sharing each row (tg dimension)
        p0 += __shfl_xor_sync(0xffffffffu, p0, 1);
        p0 += __shfl_xor_sync(0xffffffffu, p0, 2);
        p1 += __shfl_xor_sync(0xffffffffu, p1, 1);
        p1 += __shfl_xor_sync(0xffffffffu, p1, 2);

        if (tg == 0) {
            out[R + g]     = p0 + ob;
            out[R + g + 8] = p1 + ob;
        }
    }
}

extern "C" void kernel_launch(void* const* d_in, const int* in_sizes, int n_in,
                              void* d_out, int out_size) {
    const float* x     = (const float*)d_in[0];  // [B, 64]
    const float* state = (const float*)d_in[1];  // [1, 1]
    const float* inW   = (const float*)d_in[2];  // [64, 64]
    const float* stW   = (const float*)d_in[3];  // [1, 1, 64]
    const float* bias  = (const float*)d_in[4];  // [1, 64]
    const float* outW  = (const float*)d_in[5];  // [64, 1]
    const float* outb  = (const float*)d_in[6];  // [1]
    float* out = (float*)d_out;                  // [B, 1]

    int grid = out_size / ROWS_PER_CTA;          // 2097152 / 512 = 4096
    jordon_kernel<<<grid, 128>>>(x, state, inW, stW, bias, outW, outb, out);
}